// round 1
// baseline (speedup 1.0000x reference)
#include <cuda_runtime.h>
#include <math.h>

// Problem constants (fixed shapes for this problem instance)
#define CCH   256
#define NHEADS 8
#define HD     32
#define BB      2
#define TT      4
#define HH     64
#define WWID   64
#define NWIN  128          // B * 8 * 8 windows
#define LTOK  256          // T * 8 * 8 tokens per window
#define MTOT  (NWIN*LTOK)  // 32768 rows
#define ATT_SCALE 0.1767766952966369f  // 1/sqrt(32)

// -------- global scratch (no runtime allocation allowed) --------
__device__ float g_xw [MTOT * CCH];        // pre-LN gathered tokens (residual)
__device__ float g_xn [MTOT * CCH];        // LN output
__device__ float g_qkv[MTOT * 3 * CCH];    // qkv
__device__ float g_att[MTOT * CCH];        // attention output

// ============================================================
// Kernel 1: gather NCHW -> (window, token, C), LayerNorm over C
// one block per token, one thread per channel
// ============================================================
__global__ void ln_gather_kernel(const float* __restrict__ x,
                                 const float* __restrict__ gamma,
                                 const float* __restrict__ beta)
{
    int m = blockIdx.x;            // window*256 + token
    int c = threadIdx.x;           // channel
    int n = m >> 8, l = m & 255;
    int b  = n >> 6, hi = (n >> 3) & 7, wi = n & 7;
    int t  = l >> 6, r  = (l >> 3) & 7, s  = l & 7;
    int bt = b * TT + t;
    int h  = hi * 8 + r;
    int w  = wi * 8 + s;

    float val = x[(((size_t)bt * CCH + c) * HH + h) * WWID + w];

    // block reduction of sum / sumsq over 256 channels
    float sum = val, sq = val * val;
    #pragma unroll
    for (int o = 16; o > 0; o >>= 1) {
        sum += __shfl_xor_sync(0xffffffffu, sum, o);
        sq  += __shfl_xor_sync(0xffffffffu, sq,  o);
    }
    __shared__ float ssum[8], ssq[8];
    int wid = c >> 5, lid = c & 31;
    if (lid == 0) { ssum[wid] = sum; ssq[wid] = sq; }
    __syncthreads();
    float tot = 0.f, tot2 = 0.f;
    #pragma unroll
    for (int i = 0; i < 8; i++) { tot += ssum[i]; tot2 += ssq[i]; }

    float mu   = tot * (1.0f / 256.0f);
    float var  = tot2 * (1.0f / 256.0f) - mu * mu;
    float rstd = rsqrtf(var + 1e-5f);
    float xn   = (val - mu) * rstd * gamma[c] + beta[c];

    size_t o = (size_t)m * CCH + c;
    g_xw[o] = val;
    g_xn[o] = xn;
}

// ============================================================
// Kernel 2: QKV GEMM  g_qkv = g_xn(32768x256) @ w_qkv^T(256x768) + b
// 64x64 tile, BK=16, 256 threads, 4x4 microtile
// ============================================================
__global__ void gemm_qkv_kernel(const float* __restrict__ Bmat,   // w_qkv [768,256]
                                const float* __restrict__ bias)   // b_qkv [768]
{
    __shared__ float As[16][64];
    __shared__ float Bs[16][64];

    const int NN = 3 * CCH; // 768
    int mtile = blockIdx.y, ntile = blockIdx.x;
    int tid = threadIdx.x;
    int tm = tid >> 4, tn = tid & 15;

    float acc[4][4] = {};

    int lr = tid >> 2;          // 0..63 : row within tile for loading
    int lk = (tid & 3) * 4;     // k offset (float4)
    const float* Aptr = g_xn + ((size_t)mtile * 64 + lr) * 256 + lk;
    const float* Bptr = Bmat + ((size_t)ntile * 64 + lr) * 256 + lk;

    for (int kt = 0; kt < 256; kt += 16) {
        float4 av = *(const float4*)(Aptr + kt);
        float4 bv = *(const float4*)(Bptr + kt);
        __syncthreads();
        As[lk+0][lr] = av.x; As[lk+1][lr] = av.y; As[lk+2][lr] = av.z; As[lk+3][lr] = av.w;
        Bs[lk+0][lr] = bv.x; Bs[lk+1][lr] = bv.y; Bs[lk+2][lr] = bv.z; Bs[lk+3][lr] = bv.w;
        __syncthreads();
        #pragma unroll
        for (int kk = 0; kk < 16; kk++) {
            float4 a4 = *(const float4*)&As[kk][tm * 4];
            float4 b4 = *(const float4*)&Bs[kk][tn * 4];
            float a[4] = {a4.x, a4.y, a4.z, a4.w};
            float b[4] = {b4.x, b4.y, b4.z, b4.w};
            #pragma unroll
            for (int i = 0; i < 4; i++)
                #pragma unroll
                for (int j = 0; j < 4; j++)
                    acc[i][j] += a[i] * b[j];
        }
    }

    #pragma unroll
    for (int i = 0; i < 4; i++) {
        int mrow = mtile * 64 + tm * 4 + i;
        int ncol = ntile * 64 + tn * 4;
        float4 o;
        o.x = acc[i][0] + bias[ncol + 0];
        o.y = acc[i][1] + bias[ncol + 1];
        o.z = acc[i][2] + bias[ncol + 2];
        o.w = acc[i][3] + bias[ncol + 3];
        *(float4*)&g_qkv[(size_t)mrow * NN + ncol] = o;
    }
}

// ============================================================
// Kernel 3: attention per (window, head). 256 threads = 1 per query.
// streaming softmax (no max-shift: scores are O(1) here, exp is safe)
// ============================================================
__global__ void attn_kernel()
{
    __shared__ float Ks[128][32];
    __shared__ float Vs[128][32];

    int n    = blockIdx.x >> 3;
    int head = blockIdx.x & 7;
    int l    = threadIdx.x;

    const float* base = g_qkv + (size_t)n * 256 * 768;

    // load + pre-scale q
    float q[32];
    const float* qp = base + (size_t)l * 768 + head * 32;
    #pragma unroll
    for (int d = 0; d < 32; d += 4) {
        float4 v = *(const float4*)(qp + d);
        q[d+0] = v.x * ATT_SCALE; q[d+1] = v.y * ATT_SCALE;
        q[d+2] = v.z * ATT_SCALE; q[d+3] = v.w * ATT_SCALE;
    }

    float lsum = 0.f;
    float acc[32];
    #pragma unroll
    for (int d = 0; d < 32; d++) acc[d] = 0.f;

    int jr = threadIdx.x >> 3;        // 0..31
    int d4 = (threadIdx.x & 7) * 4;   // 0..28

    for (int ch = 0; ch < 2; ch++) {
        __syncthreads();
        #pragma unroll
        for (int p = 0; p < 4; p++) {
            int j = p * 32 + jr;
            const float* kp = base + (size_t)(ch * 128 + j) * 768 + 256 + head * 32 + d4;
            *(float4*)&Ks[j][d4] = *(const float4*)kp;
            *(float4*)&Vs[j][d4] = *(const float4*)(kp + 256);
        }
        __syncthreads();

        for (int j = 0; j < 128; j++) {
            float s = 0.f;
            #pragma unroll
            for (int d = 0; d < 32; d += 4) {
                float4 kv = *(const float4*)&Ks[j][d];
                s += q[d] * kv.x + q[d+1] * kv.y + q[d+2] * kv.z + q[d+3] * kv.w;
            }
            float p = __expf(s);
            lsum += p;
            #pragma unroll
            for (int d = 0; d < 32; d += 4) {
                float4 vv = *(const float4*)&Vs[j][d];
                acc[d]   += p * vv.x; acc[d+1] += p * vv.y;
                acc[d+2] += p * vv.z; acc[d+3] += p * vv.w;
            }
        }
    }

    float inv = 1.0f / lsum;
    float* op = g_att + ((size_t)n * 256 + l) * 256 + head * 32;
    #pragma unroll
    for (int d = 0; d < 32; d += 4) {
        float4 o;
        o.x = acc[d]   * inv; o.y = acc[d+1] * inv;
        o.z = acc[d+2] * inv; o.w = acc[d+3] * inv;
        *(float4*)(op + d) = o;
    }
}

// ============================================================
// Kernel 4: proj GEMM + bias + residual + scatter back to NCHW
// ============================================================
__global__ void gemm_proj_kernel(const float* __restrict__ Bmat,   // w_proj [256,256]
                                 const float* __restrict__ bias,   // b_proj [256]
                                 float* __restrict__ out)
{
    __shared__ float As[16][64];
    __shared__ float Bs[16][64];

    int mtile = blockIdx.y, ntile = blockIdx.x;
    int tid = threadIdx.x;
    int tm = tid >> 4, tn = tid & 15;

    float acc[4][4] = {};

    int lr = tid >> 2;
    int lk = (tid & 3) * 4;
    const float* Aptr = g_att + ((size_t)mtile * 64 + lr) * 256 + lk;
    const float* Bptr = Bmat + ((size_t)ntile * 64 + lr) * 256 + lk;

    for (int kt = 0; kt < 256; kt += 16) {
        float4 av = *(const float4*)(Aptr + kt);
        float4 bv = *(const float4*)(Bptr + kt);
        __syncthreads();
        As[lk+0][lr] = av.x; As[lk+1][lr] = av.y; As[lk+2][lr] = av.z; As[lk+3][lr] = av.w;
        Bs[lk+0][lr] = bv.x; Bs[lk+1][lr] = bv.y; Bs[lk+2][lr] = bv.z; Bs[lk+3][lr] = bv.w;
        __syncthreads();
        #pragma unroll
        for (int kk = 0; kk < 16; kk++) {
            float4 a4 = *(const float4*)&As[kk][tm * 4];
            float4 b4 = *(const float4*)&Bs[kk][tn * 4];
            float a[4] = {a4.x, a4.y, a4.z, a4.w};
            float b[4] = {b4.x, b4.y, b4.z, b4.w};
            #pragma unroll
            for (int i = 0; i < 4; i++)
                #pragma unroll
                for (int j = 0; j < 4; j++)
                    acc[i][j] += a[i] * b[j];
        }
    }

    #pragma unroll
    for (int i = 0; i < 4; i++) {
        int m = mtile * 64 + tm * 4 + i;
        int n = m >> 8, l = m & 255;
        int b  = n >> 6, hi = (n >> 3) & 7, wi = n & 7;
        int t  = l >> 6, r  = (l >> 3) & 7, s  = l & 7;
        int bt = b * TT + t;
        int h  = hi * 8 + r;
        int w  = wi * 8 + s;
        #pragma unroll
        for (int j = 0; j < 4; j++) {
            int c = ntile * 64 + tn * 4 + j;
            float v = acc[i][j] + bias[c] + g_xw[(size_t)m * 256 + c];
            out[(((size_t)bt * CCH + c) * HH + h) * WWID + w] = v;
        }
    }
}

// ============================================================
extern "C" void kernel_launch(void* const* d_in, const int* in_sizes, int n_in,
                              void* d_out, int out_size)
{
    const float* x      = (const float*)d_in[0];
    const float* w_qkv  = (const float*)d_in[1];
    const float* b_qkv  = (const float*)d_in[2];
    const float* w_proj = (const float*)d_in[3];
    const float* b_proj = (const float*)d_in[4];
    const float* gamma  = (const float*)d_in[5];
    const float* beta   = (const float*)d_in[6];
    float* out = (float*)d_out;

    ln_gather_kernel<<<MTOT, 256>>>(x, gamma, beta);
    gemm_qkv_kernel<<<dim3(12, 512), 256>>>(w_qkv, b_qkv);
    attn_kernel<<<NWIN * NHEADS, 256>>>();
    gemm_proj_kernel<<<dim3(4, 512), 256>>>(w_proj, b_proj, out);
}

// round 2
// speedup vs baseline: 1.7354x; 1.7354x over previous
#include <cuda_runtime.h>
#include <math.h>
#include <stdint.h>

// Problem constants (fixed shapes)
#define CCH   256
#define NHEADS 8
#define HD     32
#define TT      4
#define HH     64
#define WWID   64
#define NWIN  128
#define LTOK  256
#define MTOT  (NWIN*LTOK)  // 32768 rows
#define ATT_SCALE 0.1767766952966369f

// -------- global scratch --------
__device__ float g_xw [MTOT * CCH];
__device__ float g_xn [MTOT * CCH];
__device__ float g_qkv[MTOT * 3 * CCH];
__device__ float g_att[MTOT * CCH];

__device__ __forceinline__ float to_tf32(float x) {
    float r;
    asm("cvt.rna.tf32.f32 %0, %1;" : "=f"(r) : "f"(x));
    return r;
}

__device__ __forceinline__ void mma_tf32(float* c,
                                         uint32_t a0, uint32_t a1, uint32_t a2, uint32_t a3,
                                         uint32_t b0, uint32_t b1) {
    asm volatile("mma.sync.aligned.m16n8k8.row.col.f32.tf32.tf32.f32 "
                 "{%0,%1,%2,%3}, {%4,%5,%6,%7}, {%8,%9}, {%0,%1,%2,%3};"
                 : "+f"(c[0]), "+f"(c[1]), "+f"(c[2]), "+f"(c[3])
                 : "r"(a0), "r"(a1), "r"(a2), "r"(a3), "r"(b0), "r"(b1));
}

// ============================================================
// Kernel 1: gather NCHW -> (window, token, C), LayerNorm over C
// ============================================================
__global__ void ln_gather_kernel(const float* __restrict__ x,
                                 const float* __restrict__ gamma,
                                 const float* __restrict__ beta)
{
    int m = blockIdx.x;
    int c = threadIdx.x;
    int n = m >> 8, l = m & 255;
    int b  = n >> 6, hi = (n >> 3) & 7, wi = n & 7;
    int t  = l >> 6, r  = (l >> 3) & 7, s  = l & 7;
    int bt = b * TT + t;
    int h  = hi * 8 + r;
    int w  = wi * 8 + s;

    float val = x[(((size_t)bt * CCH + c) * HH + h) * WWID + w];

    float sum = val, sq = val * val;
    #pragma unroll
    for (int o = 16; o > 0; o >>= 1) {
        sum += __shfl_xor_sync(0xffffffffu, sum, o);
        sq  += __shfl_xor_sync(0xffffffffu, sq,  o);
    }
    __shared__ float ssum[8], ssq[8];
    int wid = c >> 5, lid = c & 31;
    if (lid == 0) { ssum[wid] = sum; ssq[wid] = sq; }
    __syncthreads();
    float tot = 0.f, tot2 = 0.f;
    #pragma unroll
    for (int i = 0; i < 8; i++) { tot += ssum[i]; tot2 += ssq[i]; }

    float mu   = tot * (1.0f / 256.0f);
    float var  = tot2 * (1.0f / 256.0f) - mu * mu;
    float rstd = rsqrtf(var + 1e-5f);
    float xn   = (val - mu) * rstd * gamma[c] + beta[c];

    size_t o = (size_t)m * CCH + c;
    g_xw[o] = val;
    g_xn[o] = xn;
}

// ============================================================
// tf32 tensor-core GEMM, block tile 128x128, BK=32, 8 warps.
// A = g_xn or g_att [M,256] row-major, B = weight [N,256] row-major
// (i.e. k-major for both -> mma row.col).
// ============================================================

// -------- QKV: C[32768,768] = A @ W^T + bias --------
__global__ __launch_bounds__(256) void gemm_qkv_mma(const float* __restrict__ Bmat,
                                                    const float* __restrict__ bias)
{
    __shared__ float As[128][36];
    __shared__ float Bs[128][36];

    int tid  = threadIdx.x;
    int lane = tid & 31, warp = tid >> 5;
    int g = lane >> 2, t = lane & 3;
    int wm = (warp & 1) * 64;
    int wn = (warp >> 1) * 32;

    const float* Ab = g_xn + (size_t)blockIdx.y * 128 * 256;
    const float* Bb = Bmat + (size_t)blockIdx.x * 128 * 256;

    int r0 = tid >> 3;            // rows r0 + 32*i
    int c4 = (tid & 7) * 4;       // k offset within BK

    float4 apf[4], bpf[4];
    #pragma unroll
    for (int i = 0; i < 4; i++) {
        apf[i] = *(const float4*)(Ab + (size_t)(r0 + 32*i) * 256 + c4);
        bpf[i] = *(const float4*)(Bb + (size_t)(r0 + 32*i) * 256 + c4);
    }

    float c[4][4][4] = {};

    for (int kt = 0; kt < 256; kt += 32) {
        __syncthreads();
        #pragma unroll
        for (int i = 0; i < 4; i++) {
            int rr = r0 + 32*i;
            float4 av = make_float4(to_tf32(apf[i].x), to_tf32(apf[i].y),
                                    to_tf32(apf[i].z), to_tf32(apf[i].w));
            float4 bv = make_float4(to_tf32(bpf[i].x), to_tf32(bpf[i].y),
                                    to_tf32(bpf[i].z), to_tf32(bpf[i].w));
            *(float4*)&As[rr][c4] = av;
            *(float4*)&Bs[rr][c4] = bv;
        }
        __syncthreads();
        if (kt + 32 < 256) {
            #pragma unroll
            for (int i = 0; i < 4; i++) {
                apf[i] = *(const float4*)(Ab + (size_t)(r0 + 32*i) * 256 + kt + 32 + c4);
                bpf[i] = *(const float4*)(Bb + (size_t)(r0 + 32*i) * 256 + kt + 32 + c4);
            }
        }
        #pragma unroll
        for (int ks = 0; ks < 4; ks++) {
            int k0 = ks * 8;
            uint32_t bf[4][2];
            #pragma unroll
            for (int j = 0; j < 4; j++) {
                bf[j][0] = __float_as_uint(Bs[wn + j*8 + g][k0 + t]);
                bf[j][1] = __float_as_uint(Bs[wn + j*8 + g][k0 + t + 4]);
            }
            #pragma unroll
            for (int m = 0; m < 4; m++) {
                int rb = wm + m*16;
                uint32_t a0 = __float_as_uint(As[rb + g    ][k0 + t    ]);
                uint32_t a1 = __float_as_uint(As[rb + g + 8][k0 + t    ]);
                uint32_t a2 = __float_as_uint(As[rb + g    ][k0 + t + 4]);
                uint32_t a3 = __float_as_uint(As[rb + g + 8][k0 + t + 4]);
                #pragma unroll
                for (int j = 0; j < 4; j++)
                    mma_tf32(c[m][j], a0, a1, a2, a3, bf[j][0], bf[j][1]);
            }
        }
    }

    int mbase = blockIdx.y * 128 + wm;
    int nbase = blockIdx.x * 128 + wn;
    #pragma unroll
    for (int m = 0; m < 4; m++) {
        int row0 = mbase + m*16 + g;
        #pragma unroll
        for (int j = 0; j < 4; j++) {
            int col = nbase + j*8 + 2*t;
            float2 bv = *(const float2*)&bias[col];
            float2 o0 = make_float2(c[m][j][0] + bv.x, c[m][j][1] + bv.y);
            float2 o1 = make_float2(c[m][j][2] + bv.x, c[m][j][3] + bv.y);
            *(float2*)&g_qkv[(size_t)row0       * 768 + col] = o0;
            *(float2*)&g_qkv[(size_t)(row0 + 8) * 768 + col] = o1;
        }
    }
}

// -------- proj: out = scatter(A @ Wp^T + bias + residual) --------
__global__ __launch_bounds__(256) void gemm_proj_mma(const float* __restrict__ Bmat,
                                                     const float* __restrict__ bias,
                                                     float* __restrict__ out)
{
    __shared__ float As[128][36];
    __shared__ float Bs[128][36];

    int tid  = threadIdx.x;
    int lane = tid & 31, warp = tid >> 5;
    int g = lane >> 2, t = lane & 3;
    int wm = (warp & 1) * 64;
    int wn = (warp >> 1) * 32;

    const float* Ab = g_att + (size_t)blockIdx.y * 128 * 256;
    const float* Bb = Bmat + (size_t)blockIdx.x * 128 * 256;

    int r0 = tid >> 3;
    int c4 = (tid & 7) * 4;

    float4 apf[4], bpf[4];
    #pragma unroll
    for (int i = 0; i < 4; i++) {
        apf[i] = *(const float4*)(Ab + (size_t)(r0 + 32*i) * 256 + c4);
        bpf[i] = *(const float4*)(Bb + (size_t)(r0 + 32*i) * 256 + c4);
    }

    float c[4][4][4] = {};

    for (int kt = 0; kt < 256; kt += 32) {
        __syncthreads();
        #pragma unroll
        for (int i = 0; i < 4; i++) {
            int rr = r0 + 32*i;
            float4 av = make_float4(to_tf32(apf[i].x), to_tf32(apf[i].y),
                                    to_tf32(apf[i].z), to_tf32(apf[i].w));
            float4 bv = make_float4(to_tf32(bpf[i].x), to_tf32(bpf[i].y),
                                    to_tf32(bpf[i].z), to_tf32(bpf[i].w));
            *(float4*)&As[rr][c4] = av;
            *(float4*)&Bs[rr][c4] = bv;
        }
        __syncthreads();
        if (kt + 32 < 256) {
            #pragma unroll
            for (int i = 0; i < 4; i++) {
                apf[i] = *(const float4*)(Ab + (size_t)(r0 + 32*i) * 256 + kt + 32 + c4);
                bpf[i] = *(const float4*)(Bb + (size_t)(r0 + 32*i) * 256 + kt + 32 + c4);
            }
        }
        #pragma unroll
        for (int ks = 0; ks < 4; ks++) {
            int k0 = ks * 8;
            uint32_t bf[4][2];
            #pragma unroll
            for (int j = 0; j < 4; j++) {
                bf[j][0] = __float_as_uint(Bs[wn + j*8 + g][k0 + t]);
                bf[j][1] = __float_as_uint(Bs[wn + j*8 + g][k0 + t + 4]);
            }
            #pragma unroll
            for (int m = 0; m < 4; m++) {
                int rb = wm + m*16;
                uint32_t a0 = __float_as_uint(As[rb + g    ][k0 + t    ]);
                uint32_t a1 = __float_as_uint(As[rb + g + 8][k0 + t    ]);
                uint32_t a2 = __float_as_uint(As[rb + g    ][k0 + t + 4]);
                uint32_t a3 = __float_as_uint(As[rb + g + 8][k0 + t + 4]);
                #pragma unroll
                for (int j = 0; j < 4; j++)
                    mma_tf32(c[m][j], a0, a1, a2, a3, bf[j][0], bf[j][1]);
            }
        }
    }

    int mbase = blockIdx.y * 128 + wm;
    int nbase = blockIdx.x * 128 + wn;
    #pragma unroll
    for (int m = 0; m < 4; m++) {
        #pragma unroll
        for (int half = 0; half < 2; half++) {
            int mrow = mbase + m*16 + g + half*8;
            int n = mrow >> 8, l = mrow & 255;
            int b  = n >> 6, hi = (n >> 3) & 7, wi = n & 7;
            int tt = l >> 6, rr = (l >> 3) & 7, ss = l & 7;
            int bt = b * TT + tt;
            int h  = hi * 8 + rr;
            int w  = wi * 8 + ss;
            size_t obase = ((size_t)bt * CCH) * (HH * WWID) + h * WWID + w;
            #pragma unroll
            for (int j = 0; j < 4; j++) {
                int col = nbase + j*8 + 2*t;
                float v0 = c[m][j][half*2 + 0] + bias[col]     + g_xw[(size_t)mrow * 256 + col];
                float v1 = c[m][j][half*2 + 1] + bias[col + 1] + g_xw[(size_t)mrow * 256 + col + 1];
                out[obase + (size_t)col       * (HH * WWID)] = v0;
                out[obase + (size_t)(col + 1) * (HH * WWID)] = v1;
            }
        }
    }
}

// ============================================================
// Kernel 3: attention per (window, head) — fp32 SIMT (unchanged)
// ============================================================
__global__ void attn_kernel()
{
    __shared__ float Ks[128][32];
    __shared__ float Vs[128][32];

    int n    = blockIdx.x >> 3;
    int head = blockIdx.x & 7;
    int l    = threadIdx.x;

    const float* base = g_qkv + (size_t)n * 256 * 768;

    float q[32];
    const float* qp = base + (size_t)l * 768 + head * 32;
    #pragma unroll
    for (int d = 0; d < 32; d += 4) {
        float4 v = *(const float4*)(qp + d);
        q[d+0] = v.x * ATT_SCALE; q[d+1] = v.y * ATT_SCALE;
        q[d+2] = v.z * ATT_SCALE; q[d+3] = v.w * ATT_SCALE;
    }

    float lsum = 0.f;
    float acc[32];
    #pragma unroll
    for (int d = 0; d < 32; d++) acc[d] = 0.f;

    int jr = threadIdx.x >> 3;
    int d4 = (threadIdx.x & 7) * 4;

    for (int ch = 0; ch < 2; ch++) {
        __syncthreads();
        #pragma unroll
        for (int p = 0; p < 4; p++) {
            int j = p * 32 + jr;
            const float* kp = base + (size_t)(ch * 128 + j) * 768 + 256 + head * 32 + d4;
            *(float4*)&Ks[j][d4] = *(const float4*)kp;
            *(float4*)&Vs[j][d4] = *(const float4*)(kp + 256);
        }
        __syncthreads();

        for (int j = 0; j < 128; j++) {
            float s = 0.f;
            #pragma unroll
            for (int d = 0; d < 32; d += 4) {
                float4 kv = *(const float4*)&Ks[j][d];
                s += q[d] * kv.x + q[d+1] * kv.y + q[d+2] * kv.z + q[d+3] * kv.w;
            }
            float p = __expf(s);
            lsum += p;
            #pragma unroll
            for (int d = 0; d < 32; d += 4) {
                float4 vv = *(const float4*)&Vs[j][d];
                acc[d]   += p * vv.x; acc[d+1] += p * vv.y;
                acc[d+2] += p * vv.z; acc[d+3] += p * vv.w;
            }
        }
    }

    float inv = 1.0f / lsum;
    float* op = g_att + ((size_t)n * 256 + l) * 256 + head * 32;
    #pragma unroll
    for (int d = 0; d < 32; d += 4) {
        float4 o;
        o.x = acc[d]   * inv; o.y = acc[d+1] * inv;
        o.z = acc[d+2] * inv; o.w = acc[d+3] * inv;
        *(float4*)(op + d) = o;
    }
}

// ============================================================
extern "C" void kernel_launch(void* const* d_in, const int* in_sizes, int n_in,
                              void* d_out, int out_size)
{
    const float* x      = (const float*)d_in[0];
    const float* w_qkv  = (const float*)d_in[1];
    const float* b_qkv  = (const float*)d_in[2];
    const float* w_proj = (const float*)d_in[3];
    const float* b_proj = (const float*)d_in[4];
    const float* gamma  = (const float*)d_in[5];
    const float* beta   = (const float*)d_in[6];
    float* out = (float*)d_out;

    ln_gather_kernel<<<MTOT, 256>>>(x, gamma, beta);
    gemm_qkv_mma<<<dim3(6, 256), 256>>>(w_qkv, b_qkv);
    attn_kernel<<<NWIN * NHEADS, 256>>>();
    gemm_proj_mma<<<dim3(2, 256), 256>>>(w_proj, b_proj, out);
}

// round 3
// speedup vs baseline: 2.8773x; 1.6580x over previous
#include <cuda_runtime.h>
#include <math.h>
#include <stdint.h>

#define CCH   256
#define TT      4
#define HH     64
#define WWID   64
#define NWIN  128
#define MTOT  (NWIN*256)
#define ATT_SCALE 0.1767766952966369f

// -------- global scratch --------
__device__ float g_xw [MTOT * CCH];
__device__ float g_xn [MTOT * CCH];          // tf32-rounded LN output
__device__ float g_qkv[MTOT * 3 * CCH];
__device__ float g_att[MTOT * CCH];          // tf32-rounded attention output
__device__ float g_wqkv[768 * 256];          // tf32-rounded weights
__device__ float g_wproj[256 * 256];

__device__ __forceinline__ float to_tf32(float x) {
    float r;
    asm("cvt.rna.tf32.f32 %0, %1;" : "=f"(r) : "f"(x));
    return r;
}

__device__ __forceinline__ void mma_tf32(float* c,
                                         uint32_t a0, uint32_t a1, uint32_t a2, uint32_t a3,
                                         uint32_t b0, uint32_t b1) {
    asm volatile("mma.sync.aligned.m16n8k8.row.col.f32.tf32.tf32.f32 "
                 "{%0,%1,%2,%3}, {%4,%5,%6,%7}, {%8,%9}, {%0,%1,%2,%3};"
                 : "+f"(c[0]), "+f"(c[1]), "+f"(c[2]), "+f"(c[3])
                 : "r"(a0), "r"(a1), "r"(a2), "r"(a3), "r"(b0), "r"(b1));
}

__device__ __forceinline__ void cpasync16(uint32_t dst, const void* src) {
    asm volatile("cp.async.ca.shared.global [%0], [%1], 16;\n" :: "r"(dst), "l"(src));
}
#define CP_COMMIT asm volatile("cp.async.commit_group;\n" ::: "memory")
#define CP_WAIT1  asm volatile("cp.async.wait_group 1;\n" ::: "memory")

// ============================================================
// Kernel 0: weight prep (fp32 -> tf32-rounded copies)
// ============================================================
__global__ void prep_weights(const float* __restrict__ wq, const float* __restrict__ wp)
{
    int i = blockIdx.x * blockDim.x + threadIdx.x;
    if (i < 768 * 256)  g_wqkv[i]  = to_tf32(wq[i]);
    if (i < 256 * 256)  g_wproj[i] = to_tf32(wp[i]);
}

// ============================================================
// Kernel 1: gather NCHW -> (window, token, C), LayerNorm over C
// ============================================================
__global__ void ln_gather_kernel(const float* __restrict__ x,
                                 const float* __restrict__ gamma,
                                 const float* __restrict__ beta)
{
    int m = blockIdx.x;
    int c = threadIdx.x;
    int n = m >> 8, l = m & 255;
    int b  = n >> 6, hi = (n >> 3) & 7, wi = n & 7;
    int t  = l >> 6, r  = (l >> 3) & 7, s  = l & 7;
    int bt = b * TT + t;
    int h  = hi * 8 + r;
    int w  = wi * 8 + s;

    float val = x[(((size_t)bt * CCH + c) * HH + h) * WWID + w];

    float sum = val, sq = val * val;
    #pragma unroll
    for (int o = 16; o > 0; o >>= 1) {
        sum += __shfl_xor_sync(0xffffffffu, sum, o);
        sq  += __shfl_xor_sync(0xffffffffu, sq,  o);
    }
    __shared__ float ssum[8], ssq[8];
    int wid = c >> 5, lid = c & 31;
    if (lid == 0) { ssum[wid] = sum; ssq[wid] = sq; }
    __syncthreads();
    float tot = 0.f, tot2 = 0.f;
    #pragma unroll
    for (int i = 0; i < 8; i++) { tot += ssum[i]; tot2 += ssq[i]; }

    float mu   = tot * (1.0f / 256.0f);
    float var  = tot2 * (1.0f / 256.0f) - mu * mu;
    float rstd = rsqrtf(var + 1e-5f);
    float xn   = (val - mu) * rstd * gamma[c] + beta[c];

    size_t o = (size_t)m * CCH + c;
    g_xw[o] = val;
    g_xn[o] = to_tf32(xn);
}

// ============================================================
// cp.async stage loader for 128x32 tiles (pitch 36)
// ============================================================
__device__ __forceinline__ void stage_load(float (*As)[36], float (*Bs)[36],
                                           const float* Ag, const float* Bg,
                                           int r0, int c4)
{
    #pragma unroll
    for (int i = 0; i < 4; i++) {
        uint32_t da = (uint32_t)__cvta_generic_to_shared(&As[r0 + 32*i][c4]);
        uint32_t db = (uint32_t)__cvta_generic_to_shared(&Bs[r0 + 32*i][c4]);
        cpasync16(da, Ag + (size_t)(r0 + 32*i) * 256 + c4);
        cpasync16(db, Bg + (size_t)(r0 + 32*i) * 256 + c4);
    }
}

// ============================================================
// Kernel 2: QKV GEMM (tf32 mma, cp.async double buffer)
// ============================================================
__global__ __launch_bounds__(256) void gemm_qkv_mma(const float* __restrict__ bias)
{
    __shared__ float As[2][128][36];
    __shared__ float Bs[2][128][36];

    int tid  = threadIdx.x;
    int lane = tid & 31, warp = tid >> 5;
    int g = lane >> 2, t = lane & 3;
    int wm = (warp & 1) * 64;
    int wn = (warp >> 1) * 32;

    const float* Ab = g_xn   + (size_t)blockIdx.y * 128 * 256;
    const float* Bb = g_wqkv + (size_t)blockIdx.x * 128 * 256;

    int r0 = tid >> 3;
    int c4 = (tid & 7) * 4;

    stage_load(As[0], Bs[0], Ab, Bb, r0, c4);
    CP_COMMIT;

    float c[4][4][4] = {};

    for (int it = 0; it < 8; it++) {
        if (it < 7)
            stage_load(As[(it+1)&1], Bs[(it+1)&1], Ab + (it+1)*32, Bb + (it+1)*32, r0, c4);
        CP_COMMIT;
        CP_WAIT1;
        __syncthreads();
        int s = it & 1;
        #pragma unroll
        for (int ks = 0; ks < 4; ks++) {
            int k0 = ks * 8;
            uint32_t bf[4][2];
            #pragma unroll
            for (int j = 0; j < 4; j++) {
                bf[j][0] = __float_as_uint(Bs[s][wn + j*8 + g][k0 + t]);
                bf[j][1] = __float_as_uint(Bs[s][wn + j*8 + g][k0 + t + 4]);
            }
            #pragma unroll
            for (int m = 0; m < 4; m++) {
                int rb = wm + m*16;
                uint32_t a0 = __float_as_uint(As[s][rb + g    ][k0 + t    ]);
                uint32_t a1 = __float_as_uint(As[s][rb + g + 8][k0 + t    ]);
                uint32_t a2 = __float_as_uint(As[s][rb + g    ][k0 + t + 4]);
                uint32_t a3 = __float_as_uint(As[s][rb + g + 8][k0 + t + 4]);
                #pragma unroll
                for (int j = 0; j < 4; j++)
                    mma_tf32(c[m][j], a0, a1, a2, a3, bf[j][0], bf[j][1]);
            }
        }
        __syncthreads();
    }

    int mbase = blockIdx.y * 128 + wm;
    int nbase = blockIdx.x * 128 + wn;
    #pragma unroll
    for (int m = 0; m < 4; m++) {
        int row0 = mbase + m*16 + g;
        #pragma unroll
        for (int j = 0; j < 4; j++) {
            int col = nbase + j*8 + 2*t;
            float2 bv = *(const float2*)&bias[col];
            float2 o0 = make_float2(c[m][j][0] + bv.x, c[m][j][1] + bv.y);
            float2 o1 = make_float2(c[m][j][2] + bv.x, c[m][j][3] + bv.y);
            *(float2*)&g_qkv[(size_t)row0       * 768 + col] = o0;
            *(float2*)&g_qkv[(size_t)(row0 + 8) * 768 + col] = o1;
        }
    }
}

// ============================================================
// Kernel 3: tensor-core attention. 1 block per window, 16 warps.
// Per head: S = Q@K^T (tf32 mma), exp in regs, P@V (tf32 mma).
// ============================================================
__global__ __launch_bounds__(512) void attn_mma()
{
    __shared__ float Qs[256][36];
    __shared__ float Ks[256][36];
    __shared__ float Vs[256][36];

    int win  = blockIdx.x;
    int tid  = threadIdx.x;
    int lane = tid & 31, warp = tid >> 5;
    int g = lane >> 2, t = lane & 3;
    bool odd = t & 1;
    int srcA = (lane & ~3) | (t >> 1);
    int srcB = srcA + 2;

    const float* base  = g_qkv + (size_t)win * 256 * 768;
    float*       obase = g_att + (size_t)win * 256 * 256;

    int lrow = tid >> 1;
    int lc0  = (tid & 1) * 16;

    for (int head = 0; head < 8; head++) {
        __syncthreads();
        const float* src = base + (size_t)lrow * 768 + head * 32 + lc0;
        #pragma unroll
        for (int i = 0; i < 4; i++) {
            float4 q4 = *(const float4*)(src + i*4);
            float4 k4 = *(const float4*)(src + 256 + i*4);
            float4 v4 = *(const float4*)(src + 512 + i*4);
            float4 qo = make_float4(to_tf32(q4.x * ATT_SCALE), to_tf32(q4.y * ATT_SCALE),
                                    to_tf32(q4.z * ATT_SCALE), to_tf32(q4.w * ATT_SCALE));
            float4 ko = make_float4(to_tf32(k4.x), to_tf32(k4.y), to_tf32(k4.z), to_tf32(k4.w));
            float4 vo = make_float4(to_tf32(v4.x), to_tf32(v4.y), to_tf32(v4.z), to_tf32(v4.w));
            *(float4*)&Qs[lrow][lc0 + i*4] = qo;
            *(float4*)&Ks[lrow][lc0 + i*4] = ko;
            *(float4*)&Vs[lrow][lc0 + i*4] = vo;
        }
        __syncthreads();

        int mrow = warp * 16;

        // Q A-fragments (16 x 32)
        uint32_t qa[4][4];
        #pragma unroll
        for (int kf = 0; kf < 4; kf++) {
            int k0 = kf * 8;
            qa[kf][0] = __float_as_uint(Qs[mrow + g    ][k0 + t    ]);
            qa[kf][1] = __float_as_uint(Qs[mrow + g + 8][k0 + t    ]);
            qa[kf][2] = __float_as_uint(Qs[mrow + g    ][k0 + t + 4]);
            qa[kf][3] = __float_as_uint(Qs[mrow + g + 8][k0 + t + 4]);
        }

        float rs0 = 0.f, rs1 = 0.f;
        float co[4][4] = {};

        #pragma unroll
        for (int ch = 0; ch < 4; ch++) {
            int kb = ch * 64;

            // S chunk: 16 x 64
            float sf[8][4];
            #pragma unroll
            for (int nf = 0; nf < 8; nf++) { sf[nf][0]=0.f; sf[nf][1]=0.f; sf[nf][2]=0.f; sf[nf][3]=0.f; }
            #pragma unroll
            for (int kf = 0; kf < 4; kf++) {
                int k0 = kf * 8;
                #pragma unroll
                for (int nf = 0; nf < 8; nf++) {
                    uint32_t b0 = __float_as_uint(Ks[kb + nf*8 + g][k0 + t    ]);
                    uint32_t b1 = __float_as_uint(Ks[kb + nf*8 + g][k0 + t + 4]);
                    mma_tf32(sf[nf], qa[kf][0], qa[kf][1], qa[kf][2], qa[kf][3], b0, b1);
                }
            }

            // exp + rowsum + C-frag -> A-frag conversion (in place)
            #pragma unroll
            for (int nf = 0; nf < 8; nf++) {
                float e0 = __expf(sf[nf][0]);
                float e1 = __expf(sf[nf][1]);
                float e2 = __expf(sf[nf][2]);
                float e3 = __expf(sf[nf][3]);
                rs0 += e0 + e1;
                rs1 += e2 + e3;
                uint32_t u0 = __float_as_uint(to_tf32(e0));
                uint32_t u1 = __float_as_uint(to_tf32(e1));
                uint32_t u2 = __float_as_uint(to_tf32(e2));
                uint32_t u3 = __float_as_uint(to_tf32(e3));
                uint32_t x0 = __shfl_sync(0xffffffffu, u0, srcA);
                uint32_t x1 = __shfl_sync(0xffffffffu, u1, srcA);
                uint32_t y0 = __shfl_sync(0xffffffffu, u0, srcB);
                uint32_t y1 = __shfl_sync(0xffffffffu, u1, srcB);
                uint32_t z0 = __shfl_sync(0xffffffffu, u2, srcA);
                uint32_t z1 = __shfl_sync(0xffffffffu, u3, srcA);
                uint32_t w0 = __shfl_sync(0xffffffffu, u2, srcB);
                uint32_t w1 = __shfl_sync(0xffffffffu, u3, srcB);
                sf[nf][0] = __uint_as_float(odd ? x1 : x0);
                sf[nf][2] = __uint_as_float(odd ? y1 : y0);
                sf[nf][1] = __uint_as_float(odd ? z1 : z0);
                sf[nf][3] = __uint_as_float(odd ? w1 : w0);
            }

            // O += P @ V  (16x64 @ 64x32)
            #pragma unroll
            for (int kf = 0; kf < 8; kf++) {
                #pragma unroll
                for (int nf = 0; nf < 4; nf++) {
                    uint32_t b0 = __float_as_uint(Vs[kb + kf*8 + t    ][nf*8 + g]);
                    uint32_t b1 = __float_as_uint(Vs[kb + kf*8 + t + 4][nf*8 + g]);
                    mma_tf32(co[nf],
                             __float_as_uint(sf[kf][0]), __float_as_uint(sf[kf][1]),
                             __float_as_uint(sf[kf][2]), __float_as_uint(sf[kf][3]),
                             b0, b1);
                }
            }
        }

        rs0 += __shfl_xor_sync(0xffffffffu, rs0, 1);
        rs0 += __shfl_xor_sync(0xffffffffu, rs0, 2);
        rs1 += __shfl_xor_sync(0xffffffffu, rs1, 1);
        rs1 += __shfl_xor_sync(0xffffffffu, rs1, 2);
        float inv0 = 1.0f / rs0;
        float inv1 = 1.0f / rs1;

        #pragma unroll
        for (int nf = 0; nf < 4; nf++) {
            int col = head * 32 + nf*8 + 2*t;
            float2 o0 = make_float2(to_tf32(co[nf][0] * inv0), to_tf32(co[nf][1] * inv0));
            float2 o1 = make_float2(to_tf32(co[nf][2] * inv1), to_tf32(co[nf][3] * inv1));
            *(float2*)&obase[(size_t)(mrow + g    ) * 256 + col] = o0;
            *(float2*)&obase[(size_t)(mrow + g + 8) * 256 + col] = o1;
        }
    }
}

// ============================================================
// Kernel 4: proj GEMM + bias + residual + scatter (cp.async)
// ============================================================
__global__ __launch_bounds__(256) void gemm_proj_mma(const float* __restrict__ bias,
                                                     float* __restrict__ out)
{
    __shared__ float As[2][128][36];
    __shared__ float Bs[2][128][36];

    int tid  = threadIdx.x;
    int lane = tid & 31, warp = tid >> 5;
    int g = lane >> 2, t = lane & 3;
    int wm = (warp & 1) * 64;
    int wn = (warp >> 1) * 32;

    const float* Ab = g_att   + (size_t)blockIdx.y * 128 * 256;
    const float* Bb = g_wproj + (size_t)blockIdx.x * 128 * 256;

    int r0 = tid >> 3;
    int c4 = (tid & 7) * 4;

    stage_load(As[0], Bs[0], Ab, Bb, r0, c4);
    CP_COMMIT;

    float c[4][4][4] = {};

    for (int it = 0; it < 8; it++) {
        if (it < 7)
            stage_load(As[(it+1)&1], Bs[(it+1)&1], Ab + (it+1)*32, Bb + (it+1)*32, r0, c4);
        CP_COMMIT;
        CP_WAIT1;
        __syncthreads();
        int s = it & 1;
        #pragma unroll
        for (int ks = 0; ks < 4; ks++) {
            int k0 = ks * 8;
            uint32_t bf[4][2];
            #pragma unroll
            for (int j = 0; j < 4; j++) {
                bf[j][0] = __float_as_uint(Bs[s][wn + j*8 + g][k0 + t]);
                bf[j][1] = __float_as_uint(Bs[s][wn + j*8 + g][k0 + t + 4]);
            }
            #pragma unroll
            for (int m = 0; m < 4; m++) {
                int rb = wm + m*16;
                uint32_t a0 = __float_as_uint(As[s][rb + g    ][k0 + t    ]);
                uint32_t a1 = __float_as_uint(As[s][rb + g + 8][k0 + t    ]);
                uint32_t a2 = __float_as_uint(As[s][rb + g    ][k0 + t + 4]);
                uint32_t a3 = __float_as_uint(As[s][rb + g + 8][k0 + t + 4]);
                #pragma unroll
                for (int j = 0; j < 4; j++)
                    mma_tf32(c[m][j], a0, a1, a2, a3, bf[j][0], bf[j][1]);
            }
        }
        __syncthreads();
    }

    int mbase = blockIdx.y * 128 + wm;
    int nbase = blockIdx.x * 128 + wn;
    #pragma unroll
    for (int m = 0; m < 4; m++) {
        #pragma unroll
        for (int half = 0; half < 2; half++) {
            int mrow = mbase + m*16 + g + half*8;
            int n = mrow >> 8, l = mrow & 255;
            int b  = n >> 6, hi = (n >> 3) & 7, wi = n & 7;
            int tt = l >> 6, rr = (l >> 3) & 7, ss = l & 7;
            int bt = b * TT + tt;
            int h  = hi * 8 + rr;
            int w  = wi * 8 + ss;
            size_t obase = ((size_t)bt * CCH) * (HH * WWID) + h * WWID + w;
            #pragma unroll
            for (int j = 0; j < 4; j++) {
                int col = nbase + j*8 + 2*t;
                float v0 = c[m][j][half*2 + 0] + bias[col]     + g_xw[(size_t)mrow * 256 + col];
                float v1 = c[m][j][half*2 + 1] + bias[col + 1] + g_xw[(size_t)mrow * 256 + col + 1];
                out[obase + (size_t)col       * (HH * WWID)] = v0;
                out[obase + (size_t)(col + 1) * (HH * WWID)] = v1;
            }
        }
    }
}

// ============================================================
extern "C" void kernel_launch(void* const* d_in, const int* in_sizes, int n_in,
                              void* d_out, int out_size)
{
    const float* x      = (const float*)d_in[0];
    const float* w_qkv  = (const float*)d_in[1];
    const float* b_qkv  = (const float*)d_in[2];
    const float* w_proj = (const float*)d_in[3];
    const float* b_proj = (const float*)d_in[4];
    const float* gamma  = (const float*)d_in[5];
    const float* beta   = (const float*)d_in[6];
    float* out = (float*)d_out;

    prep_weights<<<768, 256>>>(w_qkv, w_proj);
    ln_gather_kernel<<<MTOT, 256>>>(x, gamma, beta);
    gemm_qkv_mma<<<dim3(6, 256), 256>>>(b_qkv);
    attn_mma<<<NWIN, 512>>>();
    gemm_proj_mma<<<dim3(2, 256), 256>>>(b_proj, out);
}

// round 4
// speedup vs baseline: 3.4311x; 1.1925x over previous
#include <cuda_runtime.h>
#include <math.h>
#include <stdint.h>

#define CCH   256
#define TT      4
#define HH     64
#define WWID   64
#define NWIN  128
#define MTOT  (NWIN*256)
#define ATT_SCALE 0.1767766952966369f

// -------- global scratch --------
__device__ float g_xw [MTOT * CCH];
__device__ float g_xn [MTOT * CCH];          // tf32-rounded LN output
__device__ float g_qkv[MTOT * 3 * CCH];      // q: scaled+tf32, k/v: tf32
__device__ float g_att[MTOT * CCH];          // tf32-rounded attention output
__device__ float g_wqkv[768 * 256];          // tf32-rounded weights
__device__ float g_wproj[256 * 256];

__device__ __forceinline__ float to_tf32(float x) {
    float r;
    asm("cvt.rna.tf32.f32 %0, %1;" : "=f"(r) : "f"(x));
    return r;
}

__device__ __forceinline__ void mma_tf32(float* c,
                                         uint32_t a0, uint32_t a1, uint32_t a2, uint32_t a3,
                                         uint32_t b0, uint32_t b1) {
    asm volatile("mma.sync.aligned.m16n8k8.row.col.f32.tf32.tf32.f32 "
                 "{%0,%1,%2,%3}, {%4,%5,%6,%7}, {%8,%9}, {%0,%1,%2,%3};"
                 : "+f"(c[0]), "+f"(c[1]), "+f"(c[2]), "+f"(c[3])
                 : "r"(a0), "r"(a1), "r"(a2), "r"(a3), "r"(b0), "r"(b1));
}

__device__ __forceinline__ void cpasync16(uint32_t dst, const void* src) {
    asm volatile("cp.async.ca.shared.global [%0], [%1], 16;\n" :: "r"(dst), "l"(src));
}
#define CP_COMMIT asm volatile("cp.async.commit_group;\n" ::: "memory")
#define CP_WAIT1  asm volatile("cp.async.wait_group 1;\n" ::: "memory")
#define CP_WAIT0  asm volatile("cp.async.wait_group 0;\n" ::: "memory")

// ============================================================
// Kernel 0: weight prep (fp32 -> tf32-rounded copies)
// ============================================================
__global__ void prep_weights(const float* __restrict__ wq, const float* __restrict__ wp)
{
    int i = blockIdx.x * blockDim.x + threadIdx.x;
    if (i < 768 * 256)  g_wqkv[i]  = to_tf32(wq[i]);
    if (i < 256 * 256)  g_wproj[i] = to_tf32(wp[i]);
}

// ============================================================
// Kernel 1: coalesced gather + LayerNorm.
// One block per (bt, h) row: loads x[bt, :, h, :] (256c x 64w) coalesced,
// LN along c in smem, writes token-major coalesced.
// ============================================================
__global__ __launch_bounds__(256) void ln_gather_kernel(const float* __restrict__ x,
                                                        const float* __restrict__ gamma,
                                                        const float* __restrict__ beta)
{
    __shared__ float tile[256][65];
    __shared__ float rsum[4][64], rsq[4][64];
    __shared__ float mus[64], rstds[64];

    int bx  = blockIdx.x;
    int bt  = bx >> 6;
    int h   = bx & 63;
    int tid = threadIdx.x;

    const float* slice = x + ((size_t)bt * 256) * 4096 + h * 64;

    // coalesced load: 256c x 64w
    int cl = tid >> 4;
    int w4 = (tid & 15) * 4;
    #pragma unroll
    for (int it = 0; it < 16; it++) {
        int c = it * 16 + cl;
        float4 v = *(const float4*)(slice + (size_t)c * 4096 + w4);
        tile[c][w4 + 0] = v.x; tile[c][w4 + 1] = v.y;
        tile[c][w4 + 2] = v.z; tile[c][w4 + 3] = v.w;
    }
    __syncthreads();

    // partial reduction: 4 threads per w
    {
        int w = tid & 63, part = tid >> 6;
        float s = 0.f, q = 0.f;
        #pragma unroll
        for (int i = 0; i < 64; i++) {
            float v = tile[part * 64 + i][w];
            s += v; q += v * v;
        }
        rsum[part][w] = s; rsq[part][w] = q;
    }
    __syncthreads();
    if (tid < 64) {
        float tot = rsum[0][tid] + rsum[1][tid] + rsum[2][tid] + rsum[3][tid];
        float tq  = rsq[0][tid]  + rsq[1][tid]  + rsq[2][tid]  + rsq[3][tid];
        float mu  = tot * (1.0f / 256.0f);
        float var = tq * (1.0f / 256.0f) - mu * mu;
        mus[tid]  = mu;
        rstds[tid] = rsqrtf(var + 1e-5f);
    }
    __syncthreads();

    // write: thread = channel, loop w; coalesced stores
    int c = tid;
    float gm = gamma[c], be = beta[c];
    int b  = bt >> 2, t = bt & 3;
    int hi = h >> 3, r = h & 7;
    int nbase = b * 64 + hi * 8;
    int lbase = t * 64 + r * 8;
    #pragma unroll 8
    for (int w = 0; w < 64; w++) {
        int n = nbase + (w >> 3);
        int l = lbase + (w & 7);
        size_t m = (size_t)n * 256 + l;
        float val = tile[c][w];
        float xn  = (val - mus[w]) * rstds[w] * gm + be;
        g_xw[m * 256 + c] = val;
        g_xn[m * 256 + c] = to_tf32(xn);
    }
}

// ============================================================
// cp.async stage loader for 128x32 tiles (pitch 36)
// ============================================================
__device__ __forceinline__ void stage_load(float (*As)[36], float (*Bs)[36],
                                           const float* Ag, const float* Bg,
                                           int r0, int c4)
{
    #pragma unroll
    for (int i = 0; i < 4; i++) {
        uint32_t da = (uint32_t)__cvta_generic_to_shared(&As[r0 + 32*i][c4]);
        uint32_t db = (uint32_t)__cvta_generic_to_shared(&Bs[r0 + 32*i][c4]);
        cpasync16(da, Ag + (size_t)(r0 + 32*i) * 256 + c4);
        cpasync16(db, Bg + (size_t)(r0 + 32*i) * 256 + c4);
    }
}

// ============================================================
// Kernel 2: QKV GEMM (tf32 mma, cp.async double buffer)
// epilogue: q cols pre-scaled by ATT_SCALE, everything tf32-rounded
// ============================================================
__global__ __launch_bounds__(256) void gemm_qkv_mma(const float* __restrict__ bias)
{
    __shared__ float As[2][128][36];
    __shared__ float Bs[2][128][36];

    int tid  = threadIdx.x;
    int lane = tid & 31, warp = tid >> 5;
    int g = lane >> 2, t = lane & 3;
    int wm = (warp & 1) * 64;
    int wn = (warp >> 1) * 32;

    const float* Ab = g_xn   + (size_t)blockIdx.y * 128 * 256;
    const float* Bb = g_wqkv + (size_t)blockIdx.x * 128 * 256;

    int r0 = tid >> 3;
    int c4 = (tid & 7) * 4;

    stage_load(As[0], Bs[0], Ab, Bb, r0, c4);
    CP_COMMIT;

    float c[4][4][4] = {};

    for (int it = 0; it < 8; it++) {
        if (it < 7)
            stage_load(As[(it+1)&1], Bs[(it+1)&1], Ab + (it+1)*32, Bb + (it+1)*32, r0, c4);
        CP_COMMIT;
        CP_WAIT1;
        __syncthreads();
        int s = it & 1;
        #pragma unroll
        for (int ks = 0; ks < 4; ks++) {
            int k0 = ks * 8;
            uint32_t bf[4][2];
            #pragma unroll
            for (int j = 0; j < 4; j++) {
                bf[j][0] = __float_as_uint(Bs[s][wn + j*8 + g][k0 + t]);
                bf[j][1] = __float_as_uint(Bs[s][wn + j*8 + g][k0 + t + 4]);
            }
            #pragma unroll
            for (int m = 0; m < 4; m++) {
                int rb = wm + m*16;
                uint32_t a0 = __float_as_uint(As[s][rb + g    ][k0 + t    ]);
                uint32_t a1 = __float_as_uint(As[s][rb + g + 8][k0 + t    ]);
                uint32_t a2 = __float_as_uint(As[s][rb + g    ][k0 + t + 4]);
                uint32_t a3 = __float_as_uint(As[s][rb + g + 8][k0 + t + 4]);
                #pragma unroll
                for (int j = 0; j < 4; j++)
                    mma_tf32(c[m][j], a0, a1, a2, a3, bf[j][0], bf[j][1]);
            }
        }
        __syncthreads();
    }

    // q block (cols < 256) gets ATT_SCALE folded in; everything tf32-rounded
    float sc = (blockIdx.x < 2) ? ATT_SCALE : 1.0f;

    int mbase = blockIdx.y * 128 + wm;
    int nbase = blockIdx.x * 128 + wn;
    #pragma unroll
    for (int m = 0; m < 4; m++) {
        int row0 = mbase + m*16 + g;
        #pragma unroll
        for (int j = 0; j < 4; j++) {
            int col = nbase + j*8 + 2*t;
            float2 bv = *(const float2*)&bias[col];
            float2 o0 = make_float2(to_tf32((c[m][j][0] + bv.x) * sc),
                                    to_tf32((c[m][j][1] + bv.y) * sc));
            float2 o1 = make_float2(to_tf32((c[m][j][2] + bv.x) * sc),
                                    to_tf32((c[m][j][3] + bv.y) * sc));
            *(float2*)&g_qkv[(size_t)row0       * 768 + col] = o0;
            *(float2*)&g_qkv[(size_t)(row0 + 8) * 768 + col] = o1;
        }
    }
}

// ============================================================
// Kernel 3: tensor-core attention. One block per (window, head).
// 4 warps; K in smem (cp.async), V transposed in smem, Q from gmem.
// ============================================================
__global__ __launch_bounds__(128) void attn_mma()
{
    __shared__ float Ks[256][36];
    __shared__ float Vt[32][260];

    int win  = blockIdx.x >> 3;
    int head = blockIdx.x & 7;
    int tid  = threadIdx.x;
    int lane = tid & 31, warp = tid >> 5;
    int g = lane >> 2, t = lane & 3;
    bool odd = t & 1;
    int srcA = (lane & ~3) | (t >> 1);
    int srcB = srcA + 2;

    const float* base  = g_qkv + (size_t)win * 256 * 768 + head * 32;
    float*       obase = g_att + (size_t)win * 256 * 256;

    // --- load K (cp.async) and V (transposed) into smem ---
    int keyl = tid >> 3;            // + 16*it
    int d4   = (tid & 7) * 4;
    #pragma unroll
    for (int it = 0; it < 16; it++) {
        int key = it * 16 + keyl;
        uint32_t dst = (uint32_t)__cvta_generic_to_shared(&Ks[key][d4]);
        cpasync16(dst, base + (size_t)key * 768 + 256 + d4);
    }
    CP_COMMIT;
    #pragma unroll
    for (int it = 0; it < 16; it++) {
        int key = it * 16 + keyl;
        float4 v = *(const float4*)(base + (size_t)key * 768 + 512 + d4);
        Vt[d4 + 0][key] = v.x; Vt[d4 + 1][key] = v.y;
        Vt[d4 + 2][key] = v.z; Vt[d4 + 3][key] = v.w;
    }
    CP_WAIT0;
    __syncthreads();

    // --- each warp: 4 query m-tiles of 16 rows ---
    for (int mt = 0; mt < 4; mt++) {
        int mrow = (mt * 4 + warp) * 16;

        // Q A-fragments direct from gmem (already scaled + tf32)
        const float* qp = base + (size_t)mrow * 768;
        uint32_t qa[4][4];
        #pragma unroll
        for (int kf = 0; kf < 4; kf++) {
            int k0 = kf * 8;
            qa[kf][0] = __float_as_uint(qp[(size_t)g       * 768 + k0 + t    ]);
            qa[kf][1] = __float_as_uint(qp[(size_t)(g + 8) * 768 + k0 + t    ]);
            qa[kf][2] = __float_as_uint(qp[(size_t)g       * 768 + k0 + t + 4]);
            qa[kf][3] = __float_as_uint(qp[(size_t)(g + 8) * 768 + k0 + t + 4]);
        }

        float rs0 = 0.f, rs1 = 0.f;
        float co[4][4] = {};

        for (int ch = 0; ch < 4; ch++) {
            int kb = ch * 64;

            // S chunk: 16 x 64
            float sf[8][4];
            #pragma unroll
            for (int nf = 0; nf < 8; nf++) { sf[nf][0]=0.f; sf[nf][1]=0.f; sf[nf][2]=0.f; sf[nf][3]=0.f; }
            #pragma unroll
            for (int kf = 0; kf < 4; kf++) {
                int k0 = kf * 8;
                #pragma unroll
                for (int nf = 0; nf < 8; nf++) {
                    uint32_t b0 = __float_as_uint(Ks[kb + nf*8 + g][k0 + t    ]);
                    uint32_t b1 = __float_as_uint(Ks[kb + nf*8 + g][k0 + t + 4]);
                    mma_tf32(sf[nf], qa[kf][0], qa[kf][1], qa[kf][2], qa[kf][3], b0, b1);
                }
            }

            // exp + rowsum + C-frag -> A-frag conversion (quad shuffles)
            #pragma unroll
            for (int nf = 0; nf < 8; nf++) {
                float e0 = __expf(sf[nf][0]);
                float e1 = __expf(sf[nf][1]);
                float e2 = __expf(sf[nf][2]);
                float e3 = __expf(sf[nf][3]);
                rs0 += e0 + e1;
                rs1 += e2 + e3;
                uint32_t u0 = __float_as_uint(to_tf32(e0));
                uint32_t u1 = __float_as_uint(to_tf32(e1));
                uint32_t u2 = __float_as_uint(to_tf32(e2));
                uint32_t u3 = __float_as_uint(to_tf32(e3));
                uint32_t x0 = __shfl_sync(0xffffffffu, u0, srcA);
                uint32_t x1 = __shfl_sync(0xffffffffu, u1, srcA);
                uint32_t y0 = __shfl_sync(0xffffffffu, u0, srcB);
                uint32_t y1 = __shfl_sync(0xffffffffu, u1, srcB);
                uint32_t z0 = __shfl_sync(0xffffffffu, u2, srcA);
                uint32_t z1 = __shfl_sync(0xffffffffu, u3, srcA);
                uint32_t w0 = __shfl_sync(0xffffffffu, u2, srcB);
                uint32_t w1 = __shfl_sync(0xffffffffu, u3, srcB);
                sf[nf][0] = __uint_as_float(odd ? x1 : x0);
                sf[nf][2] = __uint_as_float(odd ? y1 : y0);
                sf[nf][1] = __uint_as_float(odd ? z1 : z0);
                sf[nf][3] = __uint_as_float(odd ? w1 : w0);
            }

            // O += P @ V  (V^T in smem: conflict-free B-frags)
            #pragma unroll
            for (int kf = 0; kf < 8; kf++) {
                #pragma unroll
                for (int nf = 0; nf < 4; nf++) {
                    uint32_t b0 = __float_as_uint(Vt[nf*8 + g][kb + kf*8 + t    ]);
                    uint32_t b1 = __float_as_uint(Vt[nf*8 + g][kb + kf*8 + t + 4]);
                    mma_tf32(co[nf],
                             __float_as_uint(sf[kf][0]), __float_as_uint(sf[kf][1]),
                             __float_as_uint(sf[kf][2]), __float_as_uint(sf[kf][3]),
                             b0, b1);
                }
            }
        }

        rs0 += __shfl_xor_sync(0xffffffffu, rs0, 1);
        rs0 += __shfl_xor_sync(0xffffffffu, rs0, 2);
        rs1 += __shfl_xor_sync(0xffffffffu, rs1, 1);
        rs1 += __shfl_xor_sync(0xffffffffu, rs1, 2);
        float inv0 = 1.0f / rs0;
        float inv1 = 1.0f / rs1;

        #pragma unroll
        for (int nf = 0; nf < 4; nf++) {
            int col = head * 32 + nf*8 + 2*t;
            float2 o0 = make_float2(to_tf32(co[nf][0] * inv0), to_tf32(co[nf][1] * inv0));
            float2 o1 = make_float2(to_tf32(co[nf][2] * inv1), to_tf32(co[nf][3] * inv1));
            *(float2*)&obase[(size_t)(mrow + g    ) * 256 + col] = o0;
            *(float2*)&obase[(size_t)(mrow + g + 8) * 256 + col] = o1;
        }
    }
}

// ============================================================
// Kernel 4: proj GEMM + bias + residual + coalesced scatter via smem
// ============================================================
__global__ __launch_bounds__(256) void gemm_proj_mma(const float* __restrict__ bias,
                                                     float* __restrict__ out)
{
    __shared__ float smem_all[2 * 2 * 128 * 36];   // As | Bs, reused as Cs
    float (*As)[128][36] = (float (*)[128][36])smem_all;
    float (*Bs)[128][36] = (float (*)[128][36])(smem_all + 2 * 128 * 36);
    float (*Cs)[130]     = (float (*)[130])smem_all;   // 128 x 130 = 16640 floats

    int tid  = threadIdx.x;
    int lane = tid & 31, warp = tid >> 5;
    int g = lane >> 2, t = lane & 3;
    int wm = (warp & 1) * 64;
    int wn = (warp >> 1) * 32;

    const float* Ab = g_att   + (size_t)blockIdx.y * 128 * 256;
    const float* Bb = g_wproj + (size_t)blockIdx.x * 128 * 256;

    int r0 = tid >> 3;
    int c4 = (tid & 7) * 4;

    stage_load(As[0], Bs[0], Ab, Bb, r0, c4);
    CP_COMMIT;

    float c[4][4][4] = {};

    for (int it = 0; it < 8; it++) {
        if (it < 7)
            stage_load(As[(it+1)&1], Bs[(it+1)&1], Ab + (it+1)*32, Bb + (it+1)*32, r0, c4);
        CP_COMMIT;
        CP_WAIT1;
        __syncthreads();
        int s = it & 1;
        #pragma unroll
        for (int ks = 0; ks < 4; ks++) {
            int k0 = ks * 8;
            uint32_t bf[4][2];
            #pragma unroll
            for (int j = 0; j < 4; j++) {
                bf[j][0] = __float_as_uint(Bs[s][wn + j*8 + g][k0 + t]);
                bf[j][1] = __float_as_uint(Bs[s][wn + j*8 + g][k0 + t + 4]);
            }
            #pragma unroll
            for (int m = 0; m < 4; m++) {
                int rb = wm + m*16;
                uint32_t a0 = __float_as_uint(As[s][rb + g    ][k0 + t    ]);
                uint32_t a1 = __float_as_uint(As[s][rb + g + 8][k0 + t    ]);
                uint32_t a2 = __float_as_uint(As[s][rb + g    ][k0 + t + 4]);
                uint32_t a3 = __float_as_uint(As[s][rb + g + 8][k0 + t + 4]);
                #pragma unroll
                for (int j = 0; j < 4; j++)
                    mma_tf32(c[m][j], a0, a1, a2, a3, bf[j][0], bf[j][1]);
            }
        }
        __syncthreads();
    }

    // stage C tile (+bias) into smem
    int nbase = blockIdx.x * 128;
    #pragma unroll
    for (int m = 0; m < 4; m++) {
        int rl = wm + m*16 + g;
        #pragma unroll
        for (int j = 0; j < 4; j++) {
            int cl = wn + j*8 + 2*t;
            float2 bv = *(const float2*)&bias[nbase + cl];
            *(float2*)&Cs[rl    ][cl] = make_float2(c[m][j][0] + bv.x, c[m][j][1] + bv.y);
            *(float2*)&Cs[rl + 8][cl] = make_float2(c[m][j][2] + bv.x, c[m][j][3] + bv.y);
        }
    }
    __syncthreads();

    // scatter: residual add + coalesced NCHW writes (float4 along w)
    int by   = blockIdx.y;
    int n    = by >> 1;
    int half = by & 1;
    int b  = n >> 6, hi = (n >> 3) & 7, wi = n & 7;

    int cc  = tid & 127;
    int trh = tid >> 7;
    #pragma unroll
    for (int tr2 = 0; tr2 < 8; tr2++) {
        int tr = tr2 * 2 + trh;
        int t2 = tr >> 3, r = tr & 7;
        int l0 = t2 * 64 + r * 8;                    // local m base of 8-chunk
        int t_full = half * 2 + t2;
        int bt = b * 4 + t_full;
        int h  = hi * 8 + r;
        int col = nbase + cc;
        size_t m0 = (size_t)by * 128 + l0;           // global row base
        size_t oaddr = (((size_t)bt * 256 + col) * 64 + h) * 64 + wi * 8;
        #pragma unroll
        for (int j = 0; j < 2; j++) {
            float4 v;
            v.x = Cs[l0 + 4*j + 0][cc] + g_xw[(m0 + 4*j + 0) * 256 + col];
            v.y = Cs[l0 + 4*j + 1][cc] + g_xw[(m0 + 4*j + 1) * 256 + col];
            v.z = Cs[l0 + 4*j + 2][cc] + g_xw[(m0 + 4*j + 2) * 256 + col];
            v.w = Cs[l0 + 4*j + 3][cc] + g_xw[(m0 + 4*j + 3) * 256 + col];
            *(float4*)&out[oaddr + 4*j] = v;
        }
    }
}

// ============================================================
extern "C" void kernel_launch(void* const* d_in, const int* in_sizes, int n_in,
                              void* d_out, int out_size)
{
    const float* x      = (const float*)d_in[0];
    const float* w_qkv  = (const float*)d_in[1];
    const float* b_qkv  = (const float*)d_in[2];
    const float* w_proj = (const float*)d_in[3];
    const float* b_proj = (const float*)d_in[4];
    const float* gamma  = (const float*)d_in[5];
    const float* beta   = (const float*)d_in[6];
    float* out = (float*)d_out;

    prep_weights<<<768, 256>>>(w_qkv, w_proj);
    ln_gather_kernel<<<512, 256>>>(x, gamma, beta);
    gemm_qkv_mma<<<dim3(6, 256), 256>>>(b_qkv);
    attn_mma<<<NWIN * 8, 128>>>();
    gemm_proj_mma<<<dim3(2, 256), 256>>>(b_proj, out);
}